// round 2
// baseline (speedup 1.0000x reference)
#include <cuda_runtime.h>

#define TT   128
#define BB   16
#define HID  1024
#define G4   4096
#define VOC  50257
#define TB   (TT*BB)                 // 2048 rows
#define LOGITS ((size_t)TB*(size_t)VOC)

// ---------------- scratch (device globals; no allocation allowed) ----------
__device__ float g_emb[TB*HID];      // embedded input          8 MB
__device__ float g_Y[2*TB*HID];      // per-layer LSTM outputs 16 MB
__device__ float g_XW[TB*G4];        // input projections      32 MB
__device__ float g_C[BB*HID];        // cell state
__device__ float g_zero[BB*HID];     // zero h0

// ---------------- packed f32x2 helpers (2x fp32 FMA rate on sm_103a) -------
__device__ __forceinline__ unsigned long long pk2(float a, float b){
    unsigned long long r;
    asm("mov.b64 %0, {%1, %2};" : "=l"(r) : "f"(a), "f"(b));
    return r;
}
__device__ __forceinline__ void upk2(unsigned long long v, float &a, float &b){
    asm("mov.b64 {%0, %1}, %2;" : "=f"(a), "=f"(b) : "l"(v));
}
__device__ __forceinline__ unsigned long long fma2(unsigned long long a,
                                                   unsigned long long b,
                                                   unsigned long long c){
    unsigned long long d;
    asm("fma.rn.f32x2 %0, %1, %2, %3;" : "=l"(d) : "l"(a), "l"(b), "l"(c));
    return d;
}

// ---------------- small utility kernels ------------------------------------
__global__ void zero_k(float* p, int n){
    for(int i = blockIdx.x*blockDim.x + threadIdx.x; i < n; i += gridDim.x*blockDim.x)
        p[i] = 0.f;
}

__global__ void embed_k(const int* __restrict__ tokens,
                        const float* __restrict__ embW,
                        float* __restrict__ X){
    int row = blockIdx.x;                    // row = t*16 + b
    int tok = tokens[row];
    const float4* src = (const float4*)(embW + (size_t)tok*HID);
    float4* dst = (float4*)(X + (size_t)row*HID);
    for(int i = threadIdx.x; i < HID/4; i += blockDim.x) dst[i] = src[i];
}

// ---------------- GEMM: C[M,N] = A[M,K] * B[N,K]^T + b1[n] (+ b2[n]) -------
// NT layout (both K-contiguous). BM=BN=128, BK=16, 256 threads, 8x8 thread
// tile with f32x2 accumulators paired over n. M,K multiples of 128/16; N ragged.
__global__ __launch_bounds__(256, 2)
void gemm_nt(const float* __restrict__ A, const float* __restrict__ Bm,
             float* __restrict__ C, const float* __restrict__ b1,
             const float* __restrict__ b2, int N, int K)
{
    __shared__ float As[16][128];
    __shared__ float Bs[16][128];
    int tid = threadIdx.x;
    int bm = blockIdx.y*128, bn = blockIdx.x*128;
    int ty = tid >> 4, tx = tid & 15;
    int m0 = ty*8, n0 = tx*8;

    unsigned long long acc[8][4];
#pragma unroll
    for(int i=0;i<8;i++)
#pragma unroll
        for(int j=0;j<4;j++) acc[i][j] = 0ull;

    int r  = tid >> 2;     // 0..63
    int c4 = tid & 3;      // float4 column within the 16-wide k tile

    for(int kt = 0; kt < K; kt += 16){
#pragma unroll
        for(int f = 0; f < 2; f++){
            int rr = r + f*64;
            float4 av = *(const float4*)(A + (size_t)(bm+rr)*K + kt + c4*4);
            As[c4*4+0][rr]=av.x; As[c4*4+1][rr]=av.y;
            As[c4*4+2][rr]=av.z; As[c4*4+3][rr]=av.w;
            int rn = bn + rr;
            float4 bv = make_float4(0.f,0.f,0.f,0.f);
            if(rn < N) bv = *(const float4*)(Bm + (size_t)rn*K + kt + c4*4);
            Bs[c4*4+0][rr]=bv.x; Bs[c4*4+1][rr]=bv.y;
            Bs[c4*4+2][rr]=bv.z; Bs[c4*4+3][rr]=bv.w;
        }
        __syncthreads();
#pragma unroll
        for(int k=0;k<16;k++){
            float a[8];
            *(float4*)(a)   = *(const float4*)&As[k][m0];
            *(float4*)(a+4) = *(const float4*)&As[k][m0+4];
            unsigned long long bd[4];
            const unsigned long long* bp = (const unsigned long long*)&Bs[k][n0];
#pragma unroll
            for(int j=0;j<4;j++) bd[j] = bp[j];
#pragma unroll
            for(int i=0;i<8;i++){
                unsigned long long ad = pk2(a[i], a[i]);
#pragma unroll
                for(int j=0;j<4;j++) acc[i][j] = fma2(ad, bd[j], acc[i][j]);
            }
        }
        __syncthreads();
    }

#pragma unroll
    for(int i=0;i<8;i++){
        size_t m = (size_t)(bm + m0 + i);
#pragma unroll
        for(int j=0;j<4;j++){
            float x, y; upk2(acc[i][j], x, y);
            int n = bn + n0 + j*2;
            if(n < N){
                float bb = b1[n] + (b2 ? b2[n] : 0.f);
                C[m*(size_t)N + n] = x + bb;
            }
            if(n+1 < N){
                float bb = b1[n+1] + (b2 ? b2[n+1] : 0.f);
                C[m*(size_t)N + n+1] = y + bb;
            }
        }
    }
}

// ---------------- fused LSTM step -------------------------------------------
// gates[b, j] = XW_t[b, j] + dot(h_prev[b,:], Whh[j,:])  then cell update.
// grid = 128 blocks (8 hidden units each => 32 gate rows), 256 threads.
// Each warp: 4 gate rows x all 16 batches, Whh streamed from L2 once per step,
// h staged in smem, f32x2 accumulators paired over batch.
__global__ void lstm_step(const float* __restrict__ hprev,
                          const float* __restrict__ Whh,
                          const float* __restrict__ XWt,
                          float* __restrict__ Cst,
                          float* __restrict__ Yout,
                          float* __restrict__ hT,
                          float* __restrict__ cT)
{
    extern __shared__ float sm[];
    float* h_s   = sm;                 // 16*1024 floats
    float* gates = sm + BB*HID;        // 4*8*16 floats
    int tid = threadIdx.x;

    { // stage h_prev
        const float4* src = (const float4*)hprev;
        float4* dst = (float4*)h_s;
        for(int i = tid; i < BB*HID/4; i += 256) dst[i] = src[i];
    }
    __syncthreads();

    int w = tid >> 5, lane = tid & 31;
    int g = w >> 1, rbase = (w & 1)*4;     // gate type, row-subrange
    int ub = blockIdx.x*8;                 // hidden-unit tile base

    const float* wr[4];
#pragma unroll
    for(int jj=0;jj<4;jj++)
        wr[jj] = Whh + (size_t)(g*HID + ub + rbase + jj)*HID;

    unsigned long long acc[4][8];
#pragma unroll
    for(int jj=0;jj<4;jj++)
#pragma unroll
        for(int p=0;p<8;p++) acc[jj][p] = 0ull;

    for(int c = 0; c < 32; c++){
        int k = c*32 + lane;
        unsigned long long hp[8];
#pragma unroll
        for(int p=0;p<8;p++)
            hp[p] = pk2(h_s[(2*p)*HID + k], h_s[(2*p+1)*HID + k]);
#pragma unroll
        for(int jj=0;jj<4;jj++){
            float wv = wr[jj][k];
            unsigned long long wd = pk2(wv, wv);
#pragma unroll
            for(int p=0;p<8;p++) acc[jj][p] = fma2(wd, hp[p], acc[jj][p]);
        }
    }

    // cross-lane reduction of 4x16 partial dots
    float red[4][16];
#pragma unroll
    for(int jj=0;jj<4;jj++)
#pragma unroll
        for(int p=0;p<8;p++) upk2(acc[jj][p], red[jj][2*p], red[jj][2*p+1]);
#pragma unroll
    for(int jj=0;jj<4;jj++)
#pragma unroll
        for(int b=0;b<16;b++)
#pragma unroll
            for(int o=16;o>0;o>>=1)
                red[jj][b] += __shfl_xor_sync(0xffffffffu, red[jj][b], o);

    if(lane < 16){
#pragma unroll
        for(int jj=0;jj<4;jj++){
            int rloc = rbase + jj;
            float gate = red[jj][lane] +
                         XWt[(size_t)lane*G4 + g*HID + ub + rloc];
            gates[(g*8 + rloc)*16 + lane] = gate;
        }
    }
    __syncthreads();

    if(tid < 128){
        int ul = tid >> 4, b = tid & 15;
        float iv = gates[(0*8+ul)*16 + b];
        float fv = gates[(1*8+ul)*16 + b];
        float gv = gates[(2*8+ul)*16 + b];
        float ov = gates[(3*8+ul)*16 + b];
        iv = 1.f/(1.f + __expf(-iv));
        fv = 1.f/(1.f + __expf(-fv));
        ov = 1.f/(1.f + __expf(-ov));
        gv = tanhf(gv);
        int u = ub + ul;
        float co = Cst[b*HID + u];
        float cn = fv*co + iv*gv;
        float hn = ov*tanhf(cn);
        Cst[b*HID + u]  = cn;
        Yout[b*HID + u] = hn;
        if(hT){ hT[b*HID + u] = hn; cT[b*HID + u] = cn; }
    }
}

// ---------------- row-wise log_softmax over 50257, in place -----------------
__global__ void logsoftmax_k(float* __restrict__ p0){
    __shared__ float red[33];
    int row = blockIdx.x;
    float* p = p0 + (size_t)row*(size_t)VOC;
    int tid = threadIdx.x, lane = tid & 31, w = tid >> 5;
    int nthr = blockDim.x, nw = nthr >> 5;

    float m = -3.4e38f;
    for(int i = tid; i < VOC; i += nthr) m = fmaxf(m, p[i]);
#pragma unroll
    for(int o=16;o>0;o>>=1) m = fmaxf(m, __shfl_xor_sync(0xffffffffu, m, o));
    if(lane == 0) red[w] = m;
    __syncthreads();
    if(tid == 0){
        float mm = red[0];
        for(int i=1;i<nw;i++) mm = fmaxf(mm, red[i]);
        red[32] = mm;
    }
    __syncthreads();
    float M = red[32];

    float s = 0.f;
    for(int i = tid; i < VOC; i += nthr) s += __expf(p[i] - M);
#pragma unroll
    for(int o=16;o>0;o>>=1) s += __shfl_xor_sync(0xffffffffu, s, o);
    __syncthreads();
    if(lane == 0) red[w] = s;
    __syncthreads();
    if(tid == 0){
        float ss = 0.f;
        for(int i=0;i<nw;i++) ss += red[i];
        red[32] = M + logf(ss);
    }
    __syncthreads();
    float lse = red[32];
    for(int i = tid; i < VOC; i += nthr) p[i] -= lse;
}

// ---------------- launcher ---------------------------------------------------
extern "C" void kernel_launch(void* const* d_in, const int* in_sizes, int n_in,
                              void* d_out, int out_size)
{
    const int*   tokens = (const int*)  d_in[0];
    const float* embW   = (const float*)d_in[1];
    const float* Wih    = (const float*)d_in[2];
    const float* Whh    = (const float*)d_in[3];
    const float* bih    = (const float*)d_in[4];
    const float* bhh    = (const float*)d_in[5];
    const float* decW   = (const float*)d_in[6];
    const float* decb   = (const float*)d_in[7];
    float* out = (float*)d_out;

    float *pEmb,*pY,*pXW,*pC,*pZ;
    cudaGetSymbolAddress((void**)&pEmb, g_emb);
    cudaGetSymbolAddress((void**)&pY,   g_Y);
    cudaGetSymbolAddress((void**)&pXW,  g_XW);
    cudaGetSymbolAddress((void**)&pC,   g_C);
    cudaGetSymbolAddress((void**)&pZ,   g_zero);

    const int STEP_SMEM = (BB*HID + 4*8*16)*4;   // 67584 B
    cudaFuncSetAttribute(lstm_step, cudaFuncAttributeMaxDynamicSharedMemorySize,
                         STEP_SMEM);

    embed_k<<<TB, 256>>>(tokens, embW, pEmb);
    zero_k<<<64, 256>>>(pZ, BB*HID);

    for(int l = 0; l < 2; l++){
        const float* Xin = (l == 0) ? pEmb : pY;            // layer0 output at pY
        float* Yl = pY + (size_t)l*TB*HID;
        zero_k<<<64, 256>>>(pC, BB*HID);
        gemm_nt<<<dim3(G4/128, TB/128), 256>>>(Xin, Wih + (size_t)l*G4*HID,
                                               pXW, bih + l*G4, bhh + l*G4,
                                               G4, HID);
        for(int t = 0; t < TT; t++){
            const float* hp = (t == 0) ? pZ : (Yl + (size_t)(t-1)*BB*HID);
            float *hT = nullptr, *cT = nullptr;
            if(t == TT-1){
                hT = out + LOGITS + (size_t)l*BB*HID;
                cT = out + LOGITS + (size_t)(2 + l)*BB*HID;
            }
            lstm_step<<<128, 256, STEP_SMEM>>>(hp, Whh + (size_t)l*G4*HID,
                                               pXW + (size_t)t*BB*G4, pC,
                                               Yl + (size_t)t*BB*HID, hT, cT);
        }
    }

    gemm_nt<<<dim3((VOC+127)/128, TB/128), 256>>>(pY + (size_t)TB*HID, decW,
                                                  out, decb, nullptr, VOC, HID);
    logsoftmax_k<<<TB, 512>>>(out);
}